// round 3
// baseline (speedup 1.0000x reference)
#include <cuda_runtime.h>
#include <cstdint>

#define NN 10000
#define EE 160000
#define FF 512

// ---------------- scratch (__device__ globals; no allocs) ----------------
__device__ __align__(16) float g_A[NN * FF];
__device__ __align__(16) float g_B[NN * FF];
__device__ float g_dis[NN];
__device__ int   g_deg[NN];
__device__ int   g_rowptr[NN + 1];
__device__ int   g_cur[NN];
__device__ int   g_srcidx[EE];
__device__ float g_ew[EE];
__device__ int   g_is64;

// ---------------- buffer selection (avoids host-side symbol queries) ----------------
__device__ __forceinline__ const float* cbuf(int sel, const float* ext) {
    return sel == 0 ? (const float*)g_A : sel == 1 ? (const float*)g_B : ext;
}
__device__ __forceinline__ float* obuf(int sel, float* ext) {
    return sel == 0 ? g_A : sel == 1 ? g_B : ext;
}

// ---------------- edge dtype detection ----------------
// If data is int64 (values < 10000), every odd 32-bit word (high half) is 0.
// If data is int32, odd words are actual node indices (P(all zero) ~ 0).
__global__ void __launch_bounds__(256) k_detect(const int* __restrict__ ei32) {
    __shared__ int red[256];
    int t = threadIdx.x;
    int acc = 0;
    for (int w = 1 + 2 * t; w < 4096; w += 512) acc |= ei32[w];
    red[t] = acc;
    __syncthreads();
    for (int off = 128; off > 0; off >>= 1) {
        if (t < off) red[t] |= red[t + off];
        __syncthreads();
    }
    if (t == 0) g_is64 = (red[0] == 0) ? 1 : 0;
}

__device__ __forceinline__ int edge_at(const void* ei, int idx) {
    if (g_is64) return (int)((const long long*)ei)[idx];
    return ((const int*)ei)[idx];
}

// ---------------- degree / normalization ----------------
__global__ void k_zero_deg() {
    int i = blockIdx.x * 256 + threadIdx.x;
    if (i < NN) g_deg[i] = 0;
}

__global__ void k_deg_acc(const void* __restrict__ ei) {
    int e = blockIdx.x * 256 + threadIdx.x;
    if (e >= EE) return;
    int c = edge_at(ei, EE + e);                 // col = target
    if ((unsigned)c < NN) atomicAdd(&g_deg[c], 1);
}

__global__ void k_dis() {
    int i = blockIdx.x * 256 + threadIdx.x;
    if (i < NN) g_dis[i] = rsqrtf(1.0f + (float)g_deg[i]);  // +1 self loop
}

// ---------------- exclusive scan of g_deg -> g_rowptr, g_cur (one block) ----------------
__global__ void __launch_bounds__(1024) k_scan() {
    __shared__ int sh[1024];
    __shared__ int carry_s;
    int t = threadIdx.x;
    if (t == 0) carry_s = 0;
    __syncthreads();
    for (int base = 0; base < NN; base += 1024) {
        int i = base + t;
        int v = (i < NN) ? g_deg[i] : 0;
        sh[t] = v;
        __syncthreads();
        for (int off = 1; off < 1024; off <<= 1) {
            int x = (t >= off) ? sh[t - off] : 0;
            __syncthreads();
            sh[t] += x;
            __syncthreads();
        }
        int excl = carry_s + sh[t] - v;
        if (i < NN) { g_rowptr[i] = excl; g_cur[i] = excl; }
        __syncthreads();
        if (t == 1023) carry_s += sh[1023];
        __syncthreads();
    }
    if (t == 0) g_rowptr[NN] = carry_s;
}

// ---------------- CSR fill ----------------
__global__ void k_fill(const void* __restrict__ ei) {
    int e = blockIdx.x * 256 + threadIdx.x;
    if (e >= EE) return;
    int r = edge_at(ei, e);
    int c = edge_at(ei, EE + e);
    if ((unsigned)r >= NN || (unsigned)c >= NN) return;
    int pos = atomicAdd(&g_cur[c], 1);
    if ((unsigned)pos < EE) {
        g_srcidx[pos] = r;
        g_ew[pos] = g_dis[r] * g_dis[c];
    }
}

// ---------------- GEMM: C[M,512] = A[M,512] @ W[512,512] ----------------
__global__ void __launch_bounds__(256) k_gemm(int selA, const float* __restrict__ extA,
                                              const float* __restrict__ W,
                                              int selC, float* __restrict__ extC, int M) {
    const float* A = cbuf(selA, extA);
    float* C = obuf(selC, extC);

    __shared__ float As[16][64];   // [k][m]
    __shared__ float Bs[16][64];   // [k][n]

    const int tid = threadIdx.x;
    const int tx = tid & 15, ty = tid >> 4;
    const int m0 = blockIdx.y * 64, n0 = blockIdx.x * 64;

    const int arow = tid >> 2, avec = tid & 3;
    const int brow = tid >> 4, bvec = tid & 15;

    const bool aval = (m0 + arow) < M;
    const float* aptr = A + (size_t)(m0 + arow) * FF + avec * 4;
    const float* bptr = W + (size_t)brow * FF + n0 + bvec * 4;

    float acc[4][4];
#pragma unroll
    for (int i = 0; i < 4; i++)
#pragma unroll
        for (int j = 0; j < 4; j++) acc[i][j] = 0.0f;

    for (int k0 = 0; k0 < FF; k0 += 16) {
        float4 av = aval ? *(const float4*)(aptr + k0)
                         : make_float4(0.f, 0.f, 0.f, 0.f);
        float4 bv = *(const float4*)(bptr + (size_t)k0 * FF);

        As[avec * 4 + 0][arow] = av.x;
        As[avec * 4 + 1][arow] = av.y;
        As[avec * 4 + 2][arow] = av.z;
        As[avec * 4 + 3][arow] = av.w;
        *(float4*)&Bs[brow][bvec * 4] = bv;
        __syncthreads();

#pragma unroll
        for (int k = 0; k < 16; k++) {
            float4 a = *(const float4*)&As[k][ty * 4];
            float4 b = *(const float4*)&Bs[k][tx * 4];
            acc[0][0] += a.x * b.x; acc[0][1] += a.x * b.y;
            acc[0][2] += a.x * b.z; acc[0][3] += a.x * b.w;
            acc[1][0] += a.y * b.x; acc[1][1] += a.y * b.y;
            acc[1][2] += a.y * b.z; acc[1][3] += a.y * b.w;
            acc[2][0] += a.z * b.x; acc[2][1] += a.z * b.y;
            acc[2][2] += a.z * b.z; acc[2][3] += a.z * b.w;
            acc[3][0] += a.w * b.x; acc[3][1] += a.w * b.y;
            acc[3][2] += a.w * b.z; acc[3][3] += a.w * b.w;
        }
        __syncthreads();
    }

#pragma unroll
    for (int i = 0; i < 4; i++) {
        int row = m0 + ty * 4 + i;
        if (row < M) {
            float4 v = make_float4(acc[i][0], acc[i][1], acc[i][2], acc[i][3]);
            *(float4*)(C + (size_t)row * FF + n0 + tx * 4) = v;
        }
    }
}

// ---------------- fused aggregation: out[i] = dis[i]^2*h[i] + sum w*h[src] + b (opt relu) ----------------
__global__ void __launch_bounds__(128) k_agg(int selH, const float* __restrict__ bias,
                                             int selOut, float* __restrict__ extOut,
                                             int relu) {
    const float* h = cbuf(selH, nullptr);
    float* out = obuf(selOut, extOut);

    __shared__ int   sh_src[128];
    __shared__ float sh_w[128];
    const int i = blockIdx.x;
    const int t = threadIdx.x;

    float d = g_dis[i];
    float w0 = d * d;
    float4 acc = ((const float4*)(h + (size_t)i * FF))[t];
    acc.x *= w0; acc.y *= w0; acc.z *= w0; acc.w *= w0;

    const int s = g_rowptr[i], e2 = g_rowptr[i + 1];
    for (int base = s; base < e2; base += 128) {
        int m = e2 - base;
        if (m > 128) m = 128;
        if (t < m) {
            sh_src[t] = g_srcidx[base + t];
            sh_w[t]   = g_ew[base + t];
        }
        __syncthreads();
#pragma unroll 4
        for (int j = 0; j < m; j++) {
            const float4 v = ((const float4*)(h + (size_t)sh_src[j] * FF))[t];
            const float w = sh_w[j];
            acc.x += v.x * w; acc.y += v.y * w;
            acc.z += v.z * w; acc.w += v.w * w;
        }
        __syncthreads();
    }

    float4 bb = ((const float4*)bias)[t];
    acc.x += bb.x; acc.y += bb.y; acc.z += bb.z; acc.w += bb.w;
    if (relu) {
        acc.x = fmaxf(acc.x, 0.f); acc.y = fmaxf(acc.y, 0.f);
        acc.z = fmaxf(acc.z, 0.f); acc.w = fmaxf(acc.w, 0.f);
    }
    ((float4*)(out + (size_t)i * FF))[t] = acc;
}

// ---------------- launcher (kernel launches ONLY) ----------------
extern "C" void kernel_launch(void* const* d_in, const int* in_sizes, int n_in,
                              void* d_out, int out_size) {
    const float* x   = (const float*)d_in[0];
    const void*  ei  = d_in[1];
    const float* W1  = (const float*)d_in[2];
    const float* b1  = (const float*)d_in[3];
    const float* W2  = (const float*)d_in[4];
    const float* b2  = (const float*)d_in[5];
    const float* W3  = (const float*)d_in[6];
    const float* b3  = (const float*)d_in[7];
    float* out       = (float*)d_out;

    const int M = NN;
    dim3 gemm_grid(FF / 64, (M + 63) / 64);

    // edge dtype detection + normalization + CSR build
    k_detect<<<1, 256>>>((const int*)ei);
    k_zero_deg<<<(NN + 255) / 256, 256>>>();
    k_deg_acc<<<(EE + 255) / 256, 256>>>(ei);
    k_dis<<<(NN + 255) / 256, 256>>>();
    k_scan<<<1, 1024>>>();
    k_fill<<<(EE + 255) / 256, 256>>>(ei);

    // Layer 1: H1 = x@W1 -> B ; X1 = agg(H1)+b1, relu -> A
    k_gemm<<<gemm_grid, 256>>>(2, x, W1, 1, nullptr, M);
    k_agg<<<NN, 128>>>(1, b1, 0, nullptr, 1);
    // Layer 2: H2 = X1@W2 -> B ; X2 = agg(H2)+b2, relu -> A
    k_gemm<<<gemm_grid, 256>>>(0, nullptr, W2, 1, nullptr, M);
    k_agg<<<NN, 128>>>(1, b2, 0, nullptr, 1);
    // Layer 3: H3 = X2@W3 -> B ; out = agg(H3)+b3 (no relu)
    k_gemm<<<gemm_grid, 256>>>(0, nullptr, W3, 1, nullptr, M);
    k_agg<<<NN, 128>>>(1, b3, 2, out, 0);
}

// round 5
// speedup vs baseline: 1.4490x; 1.4490x over previous
#include <cuda_runtime.h>
#include <cuda_bf16.h>
#include <cstdint>

#define NN 10000
#define EE 160000
#define FF 512
#define BM 128
#define BN 128
#define BK 32
#define NT 48              // 3 passes * (512/32) k-tiles
#define SROW 40            // padded smem row stride (bf16 elems)
#define SBUF (128 * SROW)  // elems per tile buffer

// ---------------- scratch (__device__ globals; no allocs) ----------------
__device__ __align__(16) float g_A[NN * FF];
__device__ __align__(16) float g_B[NN * FF];
__device__ __align__(16) __nv_bfloat16 g_Xhi[NN * FF];
__device__ __align__(16) __nv_bfloat16 g_Xlo[NN * FF];
__device__ __align__(16) __nv_bfloat16 g_Wthi[FF * FF];   // transposed: [n][k]
__device__ __align__(16) __nv_bfloat16 g_Wtlo[FF * FF];
__device__ float g_dis[NN];
__device__ int   g_deg[NN];
__device__ int   g_rowptr[NN + 1];
__device__ int   g_cur[NN];
__device__ int   g_srcidx[EE];
__device__ float g_ew[EE];
__device__ int   g_is64;

// ---------------- buffer selection ----------------
__device__ __forceinline__ const float* cbuf(int sel, const float* ext) {
    return sel == 0 ? (const float*)g_A : sel == 1 ? (const float*)g_B : ext;
}
__device__ __forceinline__ float* obuf(int sel, float* ext) {
    return sel == 0 ? g_A : sel == 1 ? g_B : ext;
}

__device__ __forceinline__ uint32_t stu32(const void* p) {
    uint32_t a;
    asm("{ .reg .u64 t; cvta.to.shared.u64 t, %1; cvt.u32.u64 %0, t; }" : "=r"(a) : "l"(p));
    return a;
}

// ---------------- edge dtype detection ----------------
__global__ void __launch_bounds__(256) k_detect(const int* __restrict__ ei32) {
    __shared__ int red[256];
    int t = threadIdx.x;
    int acc = 0;
    for (int w = 1 + 2 * t; w < 4096; w += 512) acc |= ei32[w];
    red[t] = acc;
    __syncthreads();
    for (int off = 128; off > 0; off >>= 1) {
        if (t < off) red[t] |= red[t + off];
        __syncthreads();
    }
    if (t == 0) g_is64 = (red[0] == 0) ? 1 : 0;
}

__device__ __forceinline__ int edge_at(const void* ei, int idx) {
    if (g_is64) return (int)((const long long*)ei)[idx];
    return ((const int*)ei)[idx];
}

// ---------------- degree / normalization ----------------
__global__ void k_zero_deg() {
    int i = blockIdx.x * 256 + threadIdx.x;
    if (i < NN) g_deg[i] = 0;
}
__global__ void k_deg_acc(const void* __restrict__ ei) {
    int e = blockIdx.x * 256 + threadIdx.x;
    if (e >= EE) return;
    int c = edge_at(ei, EE + e);
    if ((unsigned)c < NN) atomicAdd(&g_deg[c], 1);
}
__global__ void k_dis() {
    int i = blockIdx.x * 256 + threadIdx.x;
    if (i < NN) g_dis[i] = rsqrtf(1.0f + (float)g_deg[i]);
}

// ---------------- exclusive scan ----------------
__global__ void __launch_bounds__(1024) k_scan() {
    __shared__ int sh[1024];
    __shared__ int carry_s;
    int t = threadIdx.x;
    if (t == 0) carry_s = 0;
    __syncthreads();
    for (int base = 0; base < NN; base += 1024) {
        int i = base + t;
        int v = (i < NN) ? g_deg[i] : 0;
        sh[t] = v;
        __syncthreads();
        for (int off = 1; off < 1024; off <<= 1) {
            int x = (t >= off) ? sh[t - off] : 0;
            __syncthreads();
            sh[t] += x;
            __syncthreads();
        }
        int excl = carry_s + sh[t] - v;
        if (i < NN) { g_rowptr[i] = excl; g_cur[i] = excl; }
        __syncthreads();
        if (t == 1023) carry_s += sh[1023];
        __syncthreads();
    }
    if (t == 0) g_rowptr[NN] = carry_s;
}

// ---------------- CSR fill ----------------
__global__ void k_fill(const void* __restrict__ ei) {
    int e = blockIdx.x * 256 + threadIdx.x;
    if (e >= EE) return;
    int r = edge_at(ei, e);
    int c = edge_at(ei, EE + e);
    if ((unsigned)r >= NN || (unsigned)c >= NN) return;
    int pos = atomicAdd(&g_cur[c], 1);
    if ((unsigned)pos < EE) {
        g_srcidx[pos] = r;
        g_ew[pos] = g_dis[r] * g_dis[c];
    }
}

// ---------------- fp32 -> bf16 hi/lo split of activations ----------------
__global__ void __launch_bounds__(256) k_cvt_x(int sel, const float* __restrict__ ext) {
    const float* src = cbuf(sel, ext);
    int idx = blockIdx.x * 256 + threadIdx.x;
    if (idx >= NN * FF / 4) return;
    float4 v = ((const float4*)src)[idx];
    __nv_bfloat16 h0 = __float2bfloat16(v.x), h1 = __float2bfloat16(v.y);
    __nv_bfloat16 h2 = __float2bfloat16(v.z), h3 = __float2bfloat16(v.w);
    __nv_bfloat16 l0 = __float2bfloat16(v.x - __bfloat162float(h0));
    __nv_bfloat16 l1 = __float2bfloat16(v.y - __bfloat162float(h1));
    __nv_bfloat16 l2 = __float2bfloat16(v.z - __bfloat162float(h2));
    __nv_bfloat16 l3 = __float2bfloat16(v.w - __bfloat162float(h3));
    __nv_bfloat162* ph = (__nv_bfloat162*)(g_Xhi + (size_t)idx * 4);
    __nv_bfloat162* pl = (__nv_bfloat162*)(g_Xlo + (size_t)idx * 4);
    ph[0] = __nv_bfloat162(h0, h1); ph[1] = __nv_bfloat162(h2, h3);
    pl[0] = __nv_bfloat162(l0, l1); pl[1] = __nv_bfloat162(l2, l3);
}

// ---------------- weight transpose + hi/lo split: Wt[n][k] = W[k][n] ----------------
__global__ void __launch_bounds__(256) k_cvt_w(const float* __restrict__ W) {
    __shared__ float tile[32][33];
    int tx = threadIdx.x & 31, ty = threadIdx.x >> 5;   // 32 x 8
    int bn = blockIdx.x * 32, bk = blockIdx.y * 32;
    for (int r = ty; r < 32; r += 8)
        tile[r][tx] = W[(size_t)(bk + r) * FF + bn + tx];
    __syncthreads();
    for (int r = ty; r < 32; r += 8) {
        float v = tile[tx][r];                          // = W[bk+tx][bn+r]
        __nv_bfloat16 h = __float2bfloat16(v);
        g_Wthi[(size_t)(bn + r) * FF + bk + tx] = h;
        g_Wtlo[(size_t)(bn + r) * FF + bk + tx] = __float2bfloat16(v - __bfloat162float(h));
    }
}

// ---------------- split-bf16 GEMM via mma.sync: g_B[M,512] = X @ W ----------------
// Accumulates Xhi*Whi + Xhi*Wlo + Xlo*Whi in fp32 registers over NT=48 k-tiles.
__global__ void __launch_bounds__(256) k_gemm_mma() {
    __shared__ __align__(16) __nv_bfloat16 sA[2][SBUF];
    __shared__ __align__(16) __nv_bfloat16 sB[2][SBUF];

    const int tid = threadIdx.x;
    const int lane = tid & 31, wid = tid >> 5;
    const int n0 = blockIdx.x * BN, m0 = blockIdx.y * BM;
    const int mbase = (wid >> 2) * 64, nbase = (wid & 3) * 32;
    const uint32_t sAb = stu32(sA), sBb = stu32(sB);

    float d[4][4][4];
#pragma unroll
    for (int i = 0; i < 4; i++)
#pragma unroll
        for (int j = 0; j < 4; j++)
#pragma unroll
            for (int q = 0; q < 4; q++) d[i][j][q] = 0.0f;

    // tile loader via cp.async (zero-fills OOB rows)
    auto load_tile = [&](int it, int buf) {
        const int pass = it >> 4, kb = (it & 15) * BK;
        const __nv_bfloat16* gX = (pass == 2) ? g_Xlo : g_Xhi;
        const __nv_bfloat16* gW = (pass == 1) ? g_Wtlo : g_Wthi;
#pragma unroll
        for (int i = 0; i < 2; i++) {
            int idx = tid + i * 256;            // 0..511
            int row = idx >> 2, seg = idx & 3;  // 4 x 16B per 64B row
            uint32_t da = sAb + (buf * SBUF + row * SROW + seg * 8) * 2;
            const void* srca = gX + (size_t)(m0 + row) * FF + kb + seg * 8;
            int sz = (m0 + row) < NN ? 16 : 0;
            asm volatile("cp.async.cg.shared.global [%0], [%1], 16, %2;"
                         :: "r"(da), "l"(srca), "r"(sz));
            uint32_t db = sBb + (buf * SBUF + row * SROW + seg * 8) * 2;
            const void* srcb = gW + (size_t)(n0 + row) * FF + kb + seg * 8;
            asm volatile("cp.async.cg.shared.global [%0], [%1], 16;"
                         :: "r"(db), "l"(srcb));
        }
        asm volatile("cp.async.commit_group;" ::: "memory");
    };

    load_tile(0, 0);

    const int lrow = lane & 15, lseg = (lane >> 4) * 8;
    for (int it = 0; it < NT; it++) {
        const int buf = it & 1;
        if (it + 1 < NT) {
            load_tile(it + 1, buf ^ 1);
            asm volatile("cp.async.wait_group 1;" ::: "memory");
        } else {
            asm volatile("cp.async.wait_group 0;" ::: "memory");
        }
        __syncthreads();

        const uint32_t ab = sAb + buf * SBUF * 2;
        const uint32_t bb = sBb + buf * SBUF * 2;
#pragma unroll
        for (int kk = 0; kk < BK; kk += 16) {
            uint32_t a[4][4];
#pragma unroll
            for (int mf = 0; mf < 4; mf++) {
                uint32_t addr = ab + ((mbase + mf * 16 + lrow) * SROW + kk + lseg) * 2;
                asm volatile("ldmatrix.sync.aligned.m8n8.x4.shared.b16 {%0,%1,%2,%3}, [%4];"
                             : "=r"(a[mf][0]), "=r"(a[mf][1]), "=r"(a[mf][2]), "=r"(a[mf][3])
                             : "r"(addr));
            }
            uint32_t b[4][2];
#pragma unroll
            for (int nb = 0; nb < 2; nb++) {
                uint32_t r0, r1, r2, r3;
                uint32_t addr = bb + ((nbase + nb * 16 + lrow) * SROW + kk + lseg) * 2;
                asm volatile("ldmatrix.sync.aligned.m8n8.x4.shared.b16 {%0,%1,%2,%3}, [%4];"
                             : "=r"(r0), "=r"(r1), "=r"(r2), "=r"(r3) : "r"(addr));
                b[nb * 2][0] = r0; b[nb * 2][1] = r2;
                b[nb * 2 + 1][0] = r1; b[nb * 2 + 1][1] = r3;
            }
#pragma unroll
            for (int mf = 0; mf < 4; mf++)
#pragma unroll
                for (int nf = 0; nf < 4; nf++) {
                    asm volatile(
                        "mma.sync.aligned.m16n8k16.row.col.f32.bf16.bf16.f32 "
                        "{%0,%1,%2,%3}, {%4,%5,%6,%7}, {%8,%9}, {%0,%1,%2,%3};"
                        : "+f"(d[mf][nf][0]), "+f"(d[mf][nf][1]),
                          "+f"(d[mf][nf][2]), "+f"(d[mf][nf][3])
                        : "r"(a[mf][0]), "r"(a[mf][1]), "r"(a[mf][2]), "r"(a[mf][3]),
                          "r"(b[nf][0]), "r"(b[nf][1]));
                }
        }
        __syncthreads();
    }

    // epilogue: write fp32 result to g_B
    const int g = lane >> 2, tg = lane & 3;
#pragma unroll
    for (int mf = 0; mf < 4; mf++) {
        int row0 = m0 + mbase + mf * 16 + g;
        int row1 = row0 + 8;
#pragma unroll
        for (int nf = 0; nf < 4; nf++) {
            int col = n0 + nbase + nf * 8 + tg * 2;
            if (row0 < NN)
                *(float2*)(g_B + (size_t)row0 * FF + col) = make_float2(d[mf][nf][0], d[mf][nf][1]);
            if (row1 < NN)
                *(float2*)(g_B + (size_t)row1 * FF + col) = make_float2(d[mf][nf][2], d[mf][nf][3]);
        }
    }
}

// ---------------- fused aggregation ----------------
__global__ void __launch_bounds__(128) k_agg(int selH, const float* __restrict__ bias,
                                             int selOut, float* __restrict__ extOut,
                                             int relu) {
    const float* h = cbuf(selH, nullptr);
    float* out = obuf(selOut, extOut);

    __shared__ int   sh_src[128];
    __shared__ float sh_w[128];
    const int i = blockIdx.x;
    const int t = threadIdx.x;

    float d = g_dis[i];
    float w0 = d * d;
    float4 acc = ((const float4*)(h + (size_t)i * FF))[t];
    acc.x *= w0; acc.y *= w0; acc.z *= w0; acc.w *= w0;

    const int s = g_rowptr[i], e2 = g_rowptr[i + 1];
    for (int base = s; base < e2; base += 128) {
        int m = e2 - base;
        if (m > 128) m = 128;
        if (t < m) {
            sh_src[t] = g_srcidx[base + t];
            sh_w[t]   = g_ew[base + t];
        }
        __syncthreads();
#pragma unroll 4
        for (int j = 0; j < m; j++) {
            const float4 v = ((const float4*)(h + (size_t)sh_src[j] * FF))[t];
            const float w = sh_w[j];
            acc.x += v.x * w; acc.y += v.y * w;
            acc.z += v.z * w; acc.w += v.w * w;
        }
        __syncthreads();
    }

    float4 bb = ((const float4*)bias)[t];
    acc.x += bb.x; acc.y += bb.y; acc.z += bb.z; acc.w += bb.w;
    if (relu) {
        acc.x = fmaxf(acc.x, 0.f); acc.y = fmaxf(acc.y, 0.f);
        acc.z = fmaxf(acc.z, 0.f); acc.w = fmaxf(acc.w, 0.f);
    }
    ((float4*)(out + (size_t)i * FF))[t] = acc;
}

// ---------------- launcher (kernel launches ONLY) ----------------
extern "C" void kernel_launch(void* const* d_in, const int* in_sizes, int n_in,
                              void* d_out, int out_size) {
    const float* x   = (const float*)d_in[0];
    const void*  ei  = d_in[1];
    const float* W1  = (const float*)d_in[2];
    const float* b1  = (const float*)d_in[3];
    const float* W2  = (const float*)d_in[4];
    const float* b2  = (const float*)d_in[5];
    const float* W3  = (const float*)d_in[6];
    const float* b3  = (const float*)d_in[7];
    float* out       = (float*)d_out;

    dim3 gemm_grid(FF / BN, (NN + BM - 1) / BM);   // (4, 79)
    dim3 cvtw_grid(16, 16);
    int cvtx_blocks = (NN * FF / 4 + 255) / 256;

    // edge dtype detection + normalization + CSR build
    k_detect<<<1, 256>>>((const int*)ei);
    k_zero_deg<<<(NN + 255) / 256, 256>>>();
    k_deg_acc<<<(EE + 255) / 256, 256>>>(ei);
    k_dis<<<(NN + 255) / 256, 256>>>();
    k_scan<<<1, 1024>>>();
    k_fill<<<(EE + 255) / 256, 256>>>(ei);

    // Layer 1: H1 = x@W1 -> g_B ; X1 = agg(H1)+b1, relu -> g_A
    k_cvt_w<<<cvtw_grid, 256>>>(W1);
    k_cvt_x<<<cvtx_blocks, 256>>>(2, x);
    k_gemm_mma<<<gemm_grid, 256>>>();
    k_agg<<<NN, 128>>>(1, b1, 0, nullptr, 1);

    // Layer 2
    k_cvt_w<<<cvtw_grid, 256>>>(W2);
    k_cvt_x<<<cvtx_blocks, 256>>>(0, nullptr);
    k_gemm_mma<<<gemm_grid, 256>>>();
    k_agg<<<NN, 128>>>(1, b2, 0, nullptr, 1);

    // Layer 3 (no relu), aggregate into d_out
    k_cvt_w<<<cvtw_grid, 256>>>(W3);
    k_cvt_x<<<cvtx_blocks, 256>>>(0, nullptr);
    k_gemm_mma<<<gemm_grid, 256>>>();
    k_agg<<<NN, 128>>>(1, b3, 2, out, 0);
}

// round 6
// speedup vs baseline: 1.6761x; 1.1568x over previous
#include <cuda_runtime.h>
#include <cuda_bf16.h>
#include <cstdint>

#define NN 10000
#define EE 160000
#define FF 512
#define BM 128
#define BN 128
#define BK 16
#define NT 32              // 512/16 k-tiles
#define TILE_B 4096        // bytes per smem tile (128 rows x 32B)

// ---------------- scratch (__device__ globals; no allocs) ----------------
__device__ __align__(16) float g_B[NN * FF];
__device__ __align__(16) __nv_bfloat16 g_Xhi[NN * FF];
__device__ __align__(16) __nv_bfloat16 g_Xlo[NN * FF];
__device__ __align__(16) __nv_bfloat16 g_Wthi[FF * FF];   // transposed: [n][k]
__device__ __align__(16) __nv_bfloat16 g_Wtlo[FF * FF];
__device__ float g_dis[NN];
__device__ int   g_deg[NN];
__device__ int   g_rowptr[NN + 1];
__device__ int   g_cur[NN];
__device__ int   g_srcidx[EE];
__device__ float g_ew[EE];
__device__ int   g_is64;

__device__ __forceinline__ uint32_t stu32(const void* p) {
    uint32_t a;
    asm("{ .reg .u64 t; cvta.to.shared.u64 t, %1; cvt.u32.u64 %0, t; }" : "=r"(a) : "l"(p));
    return a;
}

// swizzled byte offset of (row r, 16B-chunk c) in a 128x16-bf16 tile
__device__ __forceinline__ uint32_t tswz(int r, int c) {
    return (uint32_t)((r * 32 + c * 16) ^ (((r >> 2) & 7) << 4));
}

// ---------------- edge dtype detection ----------------
__global__ void __launch_bounds__(256) k_detect(const int* __restrict__ ei32) {
    __shared__ int red[256];
    int t = threadIdx.x;
    int acc = 0;
    for (int w = 1 + 2 * t; w < 4096; w += 512) acc |= ei32[w];
    red[t] = acc;
    __syncthreads();
    for (int off = 128; off > 0; off >>= 1) {
        if (t < off) red[t] |= red[t + off];
        __syncthreads();
    }
    if (t == 0) g_is64 = (red[0] == 0) ? 1 : 0;
}

__device__ __forceinline__ int edge_at(const void* ei, int idx) {
    if (g_is64) return (int)((const long long*)ei)[idx];
    return ((const int*)ei)[idx];
}

// ---------------- degree / normalization ----------------
__global__ void k_zero_deg() {
    int i = blockIdx.x * 256 + threadIdx.x;
    if (i < NN) g_deg[i] = 0;
}
__global__ void k_deg_acc(const void* __restrict__ ei) {
    int e = blockIdx.x * 256 + threadIdx.x;
    if (e >= EE) return;
    int c = edge_at(ei, EE + e);
    if ((unsigned)c < NN) atomicAdd(&g_deg[c], 1);
}
__global__ void k_dis() {
    int i = blockIdx.x * 256 + threadIdx.x;
    if (i < NN) g_dis[i] = rsqrtf(1.0f + (float)g_deg[i]);
}

// ---------------- exclusive scan ----------------
__global__ void __launch_bounds__(1024) k_scan() {
    __shared__ int sh[1024];
    __shared__ int carry_s;
    int t = threadIdx.x;
    if (t == 0) carry_s = 0;
    __syncthreads();
    for (int base = 0; base < NN; base += 1024) {
        int i = base + t;
        int v = (i < NN) ? g_deg[i] : 0;
        sh[t] = v;
        __syncthreads();
        for (int off = 1; off < 1024; off <<= 1) {
            int x = (t >= off) ? sh[t - off] : 0;
            __syncthreads();
            sh[t] += x;
            __syncthreads();
        }
        int excl = carry_s + sh[t] - v;
        if (i < NN) { g_rowptr[i] = excl; g_cur[i] = excl; }
        __syncthreads();
        if (t == 1023) carry_s += sh[1023];
        __syncthreads();
    }
    if (t == 0) g_rowptr[NN] = carry_s;
}

// ---------------- CSR fill ----------------
__global__ void k_fill(const void* __restrict__ ei) {
    int e = blockIdx.x * 256 + threadIdx.x;
    if (e >= EE) return;
    int r = edge_at(ei, e);
    int c = edge_at(ei, EE + e);
    if ((unsigned)r >= NN || (unsigned)c >= NN) return;
    int pos = atomicAdd(&g_cur[c], 1);
    if ((unsigned)pos < EE) {
        g_srcidx[pos] = r;
        g_ew[pos] = g_dis[r] * g_dis[c];
    }
}

// ---------------- fp32 -> bf16 hi/lo split of the input x (layer 1 only) ----------------
__global__ void __launch_bounds__(256) k_cvt_x(const float* __restrict__ src) {
    int idx = blockIdx.x * 256 + threadIdx.x;
    if (idx >= NN * FF / 4) return;
    float4 v = ((const float4*)src)[idx];
    __nv_bfloat16 h0 = __float2bfloat16(v.x), h1 = __float2bfloat16(v.y);
    __nv_bfloat16 h2 = __float2bfloat16(v.z), h3 = __float2bfloat16(v.w);
    __nv_bfloat16 l0 = __float2bfloat16(v.x - __bfloat162float(h0));
    __nv_bfloat16 l1 = __float2bfloat16(v.y - __bfloat162float(h1));
    __nv_bfloat16 l2 = __float2bfloat16(v.z - __bfloat162float(h2));
    __nv_bfloat16 l3 = __float2bfloat16(v.w - __bfloat162float(h3));
    __nv_bfloat162* ph = (__nv_bfloat162*)(g_Xhi + (size_t)idx * 4);
    __nv_bfloat162* pl = (__nv_bfloat162*)(g_Xlo + (size_t)idx * 4);
    ph[0] = __nv_bfloat162(h0, h1); ph[1] = __nv_bfloat162(h2, h3);
    pl[0] = __nv_bfloat162(l0, l1); pl[1] = __nv_bfloat162(l2, l3);
}

// ---------------- weight transpose + hi/lo split: Wt[n][k] = W[k][n] ----------------
__global__ void __launch_bounds__(256) k_cvt_w(const float* __restrict__ W) {
    __shared__ float tile[32][33];
    int tx = threadIdx.x & 31, ty = threadIdx.x >> 5;
    int bn = blockIdx.x * 32, bk = blockIdx.y * 32;
    for (int r = ty; r < 32; r += 8)
        tile[r][tx] = W[(size_t)(bk + r) * FF + bn + tx];
    __syncthreads();
    for (int r = ty; r < 32; r += 8) {
        float v = tile[tx][r];
        __nv_bfloat16 h = __float2bfloat16(v);
        g_Wthi[(size_t)(bn + r) * FF + bk + tx] = h;
        g_Wtlo[(size_t)(bn + r) * FF + bk + tx] = __float2bfloat16(v - __bfloat162float(h));
    }
}

// ---------------- fused split-bf16 GEMM: g_B = Xhi*Whi + Xhi*Wlo + Xlo*Whi ----------------
__global__ void __launch_bounds__(256) k_gemm_mma() {
    // [buf][tile: 0=Xhi 1=Xlo 2=Whi 3=Wlo][2048 bf16]
    __shared__ __align__(16) __nv_bfloat16 sm[2][4][2048];

    const int tid = threadIdx.x;
    const int lane = tid & 31, wid = tid >> 5;
    const int n0 = blockIdx.x * BN, m0 = blockIdx.y * BM;
    const int mbase = (wid >> 2) * 64, nbase = (wid & 3) * 32;
    const uint32_t smb = stu32(sm);

    float d[4][4][4];
#pragma unroll
    for (int i = 0; i < 4; i++)
#pragma unroll
        for (int j = 0; j < 4; j++)
#pragma unroll
            for (int q = 0; q < 4; q++) d[i][j][q] = 0.0f;

    const int lrow = tid >> 1, lch = tid & 1;  // loader mapping
    auto load_tiles = [&](int it, int buf) {
        const int kb = it * BK;
        uint32_t dst = smb + buf * (4 * TILE_B) + tswz(lrow, lch);
        const size_t xoff = (size_t)(m0 + lrow) * FF + kb + lch * 8;
        const size_t woff = (size_t)(n0 + lrow) * FF + kb + lch * 8;
        int szx = (m0 + lrow) < NN ? 16 : 0;
        asm volatile("cp.async.cg.shared.global [%0], [%1], 16, %2;"
                     :: "r"(dst + 0 * TILE_B), "l"((const void*)(g_Xhi + xoff)), "r"(szx));
        asm volatile("cp.async.cg.shared.global [%0], [%1], 16, %2;"
                     :: "r"(dst + 1 * TILE_B), "l"((const void*)(g_Xlo + xoff)), "r"(szx));
        asm volatile("cp.async.cg.shared.global [%0], [%1], 16;"
                     :: "r"(dst + 2 * TILE_B), "l"((const void*)(g_Wthi + woff)));
        asm volatile("cp.async.cg.shared.global [%0], [%1], 16;"
                     :: "r"(dst + 3 * TILE_B), "l"((const void*)(g_Wtlo + woff)));
        asm volatile("cp.async.commit_group;" ::: "memory");
    };

    load_tiles(0, 0);

    const int frow = lane & 15, fch = lane >> 4;   // fragment lane mapping
    for (int it = 0; it < NT; it++) {
        const int buf = it & 1;
        if (it + 1 < NT) {
            load_tiles(it + 1, buf ^ 1);
            asm volatile("cp.async.wait_group 1;" ::: "memory");
        } else {
            asm volatile("cp.async.wait_group 0;" ::: "memory");
        }
        __syncthreads();

        const uint32_t base = smb + buf * (4 * TILE_B);
        uint32_t aHi[4][4], aLo[4][4], bHi[4][2], bLo[4][2];
#pragma unroll
        for (int mf = 0; mf < 4; mf++) {
            uint32_t off = tswz(mbase + mf * 16 + frow, fch);
            asm volatile("ldmatrix.sync.aligned.m8n8.x4.shared.b16 {%0,%1,%2,%3}, [%4];"
                         : "=r"(aHi[mf][0]), "=r"(aHi[mf][1]), "=r"(aHi[mf][2]), "=r"(aHi[mf][3])
                         : "r"(base + 0 * TILE_B + off));
            asm volatile("ldmatrix.sync.aligned.m8n8.x4.shared.b16 {%0,%1,%2,%3}, [%4];"
                         : "=r"(aLo[mf][0]), "=r"(aLo[mf][1]), "=r"(aLo[mf][2]), "=r"(aLo[mf][3])
                         : "r"(base + 1 * TILE_B + off));
        }
#pragma unroll
        for (int nb = 0; nb < 2; nb++) {
            uint32_t off = tswz(nbase + nb * 16 + frow, fch);
            uint32_t r0, r1, r2, r3;
            asm volatile("ldmatrix.sync.aligned.m8n8.x4.shared.b16 {%0,%1,%2,%3}, [%4];"
                         : "=r"(r0), "=r"(r1), "=r"(r2), "=r"(r3)
                         : "r"(base + 2 * TILE_B + off));
            bHi[nb * 2][0] = r0; bHi[nb * 2][1] = r2;
            bHi[nb * 2 + 1][0] = r1; bHi[nb * 2 + 1][1] = r3;
            asm volatile("ldmatrix.sync.aligned.m8n8.x4.shared.b16 {%0,%1,%2,%3}, [%4];"
                         : "=r"(r0), "=r"(r1), "=r"(r2), "=r"(r3)
                         : "r"(base + 3 * TILE_B + off));
            bLo[nb * 2][0] = r0; bLo[nb * 2][1] = r2;
            bLo[nb * 2 + 1][0] = r1; bLo[nb * 2 + 1][1] = r3;
        }

#define MMA(A, B, mf, nf)                                                         \
        asm volatile(                                                             \
            "mma.sync.aligned.m16n8k16.row.col.f32.bf16.bf16.f32 "                \
            "{%0,%1,%2,%3}, {%4,%5,%6,%7}, {%8,%9}, {%0,%1,%2,%3};"               \
            : "+f"(d[mf][nf][0]), "+f"(d[mf][nf][1]),                             \
              "+f"(d[mf][nf][2]), "+f"(d[mf][nf][3])                              \
            : "r"(A[mf][0]), "r"(A[mf][1]), "r"(A[mf][2]), "r"(A[mf][3]),         \
              "r"(B[nf][0]), "r"(B[nf][1]))
#pragma unroll
        for (int mf = 0; mf < 4; mf++)
#pragma unroll
            for (int nf = 0; nf < 4; nf++) {
                MMA(aHi, bHi, mf, nf);
                MMA(aHi, bLo, mf, nf);
                MMA(aLo, bHi, mf, nf);
            }
#undef MMA
        __syncthreads();
    }

    // epilogue: write fp32 result to g_B
    const int g = lane >> 2, tg = lane & 3;
#pragma unroll
    for (int mf = 0; mf < 4; mf++) {
        int row0 = m0 + mbase + mf * 16 + g;
        int row1 = row0 + 8;
#pragma unroll
        for (int nf = 0; nf < 4; nf++) {
            int col = n0 + nbase + nf * 8 + tg * 2;
            if (row0 < NN)
                *(float2*)(g_B + (size_t)row0 * FF + col) = make_float2(d[mf][nf][0], d[mf][nf][1]);
            if (row1 < NN)
                *(float2*)(g_B + (size_t)row1 * FF + col) = make_float2(d[mf][nf][2], d[mf][nf][3]);
        }
    }
}

// ---------------- fused aggregation (reads g_B; writes hi/lo or fp32) ----------------
// mode 1: out = relu(agg + b) -> g_Xhi/g_Xlo (bf16 split, feeds next GEMM)
// mode 0: out = agg + b       -> extOut (fp32, final layer)
__global__ void __launch_bounds__(128) k_agg(const float* __restrict__ bias,
                                             int mode, float* __restrict__ extOut) {
    const float* h = g_B;
    __shared__ int   sh_src[128];
    __shared__ float sh_w[128];
    const int i = blockIdx.x;
    const int t = threadIdx.x;

    float dd = g_dis[i];
    float w0 = dd * dd;
    float4 acc = ((const float4*)(h + (size_t)i * FF))[t];
    acc.x *= w0; acc.y *= w0; acc.z *= w0; acc.w *= w0;

    const int s = g_rowptr[i], e2 = g_rowptr[i + 1];
    for (int base = s; base < e2; base += 128) {
        int m = e2 - base;
        if (m > 128) m = 128;
        if (t < m) {
            sh_src[t] = g_srcidx[base + t];
            sh_w[t]   = g_ew[base + t];
        }
        __syncthreads();
#pragma unroll 4
        for (int j = 0; j < m; j++) {
            const float4 v = ((const float4*)(h + (size_t)sh_src[j] * FF))[t];
            const float w = sh_w[j];
            acc.x += v.x * w; acc.y += v.y * w;
            acc.z += v.z * w; acc.w += v.w * w;
        }
        __syncthreads();
    }

    float4 bb = ((const float4*)bias)[t];
    acc.x += bb.x; acc.y += bb.y; acc.z += bb.z; acc.w += bb.w;

    if (mode) {
        acc.x = fmaxf(acc.x, 0.f); acc.y = fmaxf(acc.y, 0.f);
        acc.z = fmaxf(acc.z, 0.f); acc.w = fmaxf(acc.w, 0.f);
        __nv_bfloat16 h0 = __float2bfloat16(acc.x), h1 = __float2bfloat16(acc.y);
        __nv_bfloat16 h2 = __float2bfloat16(acc.z), h3 = __float2bfloat16(acc.w);
        __nv_bfloat16 l0 = __float2bfloat16(acc.x - __bfloat162float(h0));
        __nv_bfloat16 l1 = __float2bfloat16(acc.y - __bfloat162float(h1));
        __nv_bfloat16 l2 = __float2bfloat16(acc.z - __bfloat162float(h2));
        __nv_bfloat16 l3 = __float2bfloat16(acc.w - __bfloat162float(h3));
        size_t o = (size_t)i * FF + t * 4;
        __nv_bfloat162* ph = (__nv_bfloat162*)(g_Xhi + o);
        __nv_bfloat162* pl = (__nv_bfloat162*)(g_Xlo + o);
        ph[0] = __nv_bfloat162(h0, h1); ph[1] = __nv_bfloat162(h2, h3);
        pl[0] = __nv_bfloat162(l0, l1); pl[1] = __nv_bfloat162(l2, l3);
    } else {
        ((float4*)(extOut + (size_t)i * FF))[t] = acc;
    }
}

// ---------------- launcher (kernel launches ONLY) ----------------
extern "C" void kernel_launch(void* const* d_in, const int* in_sizes, int n_in,
                              void* d_out, int out_size) {
    const float* x   = (const float*)d_in[0];
    const void*  ei  = d_in[1];
    const float* W1  = (const float*)d_in[2];
    const float* b1  = (const float*)d_in[3];
    const float* W2  = (const float*)d_in[4];
    const float* b2  = (const float*)d_in[5];
    const float* W3  = (const float*)d_in[6];
    const float* b3  = (const float*)d_in[7];
    float* out       = (float*)d_out;

    dim3 gemm_grid(FF / BN, (NN + BM - 1) / BM);   // (4, 79)
    dim3 cvtw_grid(16, 16);
    int cvtx_blocks = (NN * FF / 4 + 255) / 256;

    // edge dtype detection + normalization + CSR build
    k_detect<<<1, 256>>>((const int*)ei);
    k_zero_deg<<<(NN + 255) / 256, 256>>>();
    k_deg_acc<<<(EE + 255) / 256, 256>>>(ei);
    k_dis<<<(NN + 255) / 256, 256>>>();
    k_scan<<<1, 1024>>>();
    k_fill<<<(EE + 255) / 256, 256>>>(ei);

    // Layer 1
    k_cvt_w<<<cvtw_grid, 256>>>(W1);
    k_cvt_x<<<cvtx_blocks, 256>>>(x);
    k_gemm_mma<<<gemm_grid, 256>>>();
    k_agg<<<NN, 128>>>(b1, 1, nullptr);
    // Layer 2
    k_cvt_w<<<cvtw_grid, 256>>>(W2);
    k_gemm_mma<<<gemm_grid, 256>>>();
    k_agg<<<NN, 128>>>(b2, 1, nullptr);
    // Layer 3 (final, fp32 out, no relu)
    k_cvt_w<<<cvtw_grid, 256>>>(W3);
    k_gemm_mma<<<gemm_grid, 256>>>();
    k_agg<<<NN, 128>>>(b3, 0, out);
}